// round 14
// baseline (speedup 1.0000x reference)
#include <cuda_runtime.h>
#include <math.h>

#define B_    32
#define S_    512
#define IN_   1024
#define H_    1024
#define OUT_  1024
#define G4_   4096   // 4*H
#define NBLK  128

// ---------------- scratch (device globals; no allocation allowed) ----------
__device__ float g_GX[(size_t)S_ * B_ * G4_];   // [t][b][4H] pre-activations from x-part (+bias)
__device__ float g_HS[(size_t)B_ * S_ * H_];    // [b][t][H]  hidden outputs
__device__ float g_hbuf[2][B_ * H_];            // double-buffered h
__device__ float g_c[B_ * H_];                  // cell state
__device__ unsigned g_bar;                      // grid barrier counter

// ---------------- f32x2 packed helpers ------------------------------------
__device__ __forceinline__ unsigned long long splat2(float v) {
    unsigned long long r;
    asm("mov.b64 %0, {%1, %1};" : "=l"(r) : "f"(v));
    return r;
}
__device__ __forceinline__ void fma2(unsigned long long& d, unsigned long long a, unsigned long long b) {
    asm("fma.rn.f32x2 %0, %1, %2, %0;" : "+l"(d) : "l"(a), "l"(b));
}
__device__ __forceinline__ float2 unpack2(unsigned long long v) {
    float2 r;
    asm("mov.b64 {%0, %1}, %2;" : "=f"(r.x), "=f"(r.y) : "l"(v));
    return r;
}

// ---------------- init: zero h0, c0, barrier -------------------------------
__global__ void init_state_kernel() {
    int i = blockIdx.x * blockDim.x + threadIdx.x;
    if (i < B_ * H_) {
        g_hbuf[0][i] = 0.0f;
        g_c[i] = 0.0f;
    }
    if (i == 0) g_bar = 0u;
}

// ---------------- Phase 1: GX[t*32+b][n] = x[b,t,:] @ Wx[n,:].T + bias[n] --
__global__ __launch_bounds__(256) void gx_gemm(
    const float* __restrict__ x,
    const float* __restrict__ Wf, const float* __restrict__ Wi,
    const float* __restrict__ Wc, const float* __restrict__ Wo,
    const float* __restrict__ bf, const float* __restrict__ bi,
    const float* __restrict__ bc, const float* __restrict__ bo)
{
    __shared__ float As[16][68];
    __shared__ float Bs[16][68];

    const int tid = threadIdx.x;
    const int m0 = blockIdx.y * 64;
    const int n0 = blockIdx.x * 64;
    const int tx = tid & 15;
    const int ty = tid >> 4;

    const int lrow = tid >> 2;
    const int lkq  = (tid & 3) * 4;

    const int nl = n0 + lrow;
    const int gg = nl >> 10;
    const int jw = nl & 1023;
    const float* Wg = (gg == 0) ? Wf : ((gg == 1) ? Wi : ((gg == 2) ? Wc : Wo));
    const float* wrow = Wg + (size_t)jw * 2048 + 1024;   // x-part columns
    const float* arow = x + (size_t)(m0 + lrow) * 1024;

    unsigned long long acc[4][2];
#pragma unroll
    for (int r = 0; r < 4; ++r) { acc[r][0] = 0ull; acc[r][1] = 0ull; }

    for (int k0 = 0; k0 < 1024; k0 += 16) {
        float4 av = *(const float4*)(arow + k0 + lkq);
        float4 bv = *(const float4*)(wrow + k0 + lkq);
        As[lkq + 0][lrow] = av.x; As[lkq + 1][lrow] = av.y;
        As[lkq + 2][lrow] = av.z; As[lkq + 3][lrow] = av.w;
        Bs[lkq + 0][lrow] = bv.x; Bs[lkq + 1][lrow] = bv.y;
        Bs[lkq + 2][lrow] = bv.z; Bs[lkq + 3][lrow] = bv.w;
        __syncthreads();
#pragma unroll
        for (int k = 0; k < 16; ++k) {
            float4 a4 = *(const float4*)&As[k][ty * 4];
            ulonglong2 b2 = *(const ulonglong2*)&Bs[k][tx * 4];
            unsigned long long a0 = splat2(a4.x);
            unsigned long long a1 = splat2(a4.y);
            unsigned long long a2 = splat2(a4.z);
            unsigned long long a3 = splat2(a4.w);
            fma2(acc[0][0], a0, b2.x); fma2(acc[0][1], a0, b2.y);
            fma2(acc[1][0], a1, b2.x); fma2(acc[1][1], a1, b2.y);
            fma2(acc[2][0], a2, b2.x); fma2(acc[2][1], a2, b2.y);
            fma2(acc[3][0], a3, b2.x); fma2(acc[3][1], a3, b2.y);
        }
        __syncthreads();
    }

    float bias[4];
#pragma unroll
    for (int c = 0; c < 4; ++c) {
        int n = n0 + tx * 4 + c;
        int g2 = n >> 10, j2 = n & 1023;
        const float* bb = (g2 == 0) ? bf : ((g2 == 1) ? bi : ((g2 == 2) ? bc : bo));
        bias[c] = bb[j2];
    }
#pragma unroll
    for (int r = 0; r < 4; ++r) {
        int m = m0 + ty * 4 + r;
        int b  = m >> 9;
        int tt = m & 511;
        size_t row = (size_t)tt * B_ + b;
        float2 p0 = unpack2(acc[r][0]);
        float2 p1 = unpack2(acc[r][1]);
        float4 v = make_float4(p0.x + bias[0], p0.y + bias[1],
                               p1.x + bias[2], p1.y + bias[3]);
        *(float4*)&g_GX[row * G4_ + n0 + tx * 4] = v;
    }
}

// ---------------- Phase 2: persistent recurrent kernel ---------------------
// 128 blocks (block bk owns hidden cols j in [bk*8, bk*8+8), all 4 gates),
// 256 threads = 8 warps (kg = k-slice of 128) x 32 lanes (out = (gate, jj)).
// Each thread holds its 128 recurrent weights in 32 ulonglong2 REGISTERS for
// the whole sequence. Per step: warp stages its 16KB h-slice into smem,
// computes 32 batches x 1 output over its k-slice with f32x2 FMAs (h via
// conflict-free LDS.128 broadcast), reduces across kg through padded smem,
// applies the cell update, then crosses a release/acquire grid barrier.
__global__ __launch_bounds__(256, 1) void lstm_persistent(
    const float* __restrict__ Wf, const float* __restrict__ Wi,
    const float* __restrict__ Wc, const float* __restrict__ Wo)
{
    extern __shared__ float sm[];
    float* hs  = sm;                    // [32][1024]          = 32768 floats
    float* red = sm + 32768;            // [8 kg][32 out][9]   =  2304 floats
    float* pre = sm + 32768 + 2304;     // [4 g][32 b][8 jj]   =  1024 floats

    const int tid  = threadIdx.x;
    const int kg   = tid >> 5;          // warp id = k-slice (0..7)
    const int lane = tid & 31;          // out = (g, jj)
    const int g    = lane >> 3;
    const int jj   = lane & 7;
    const int j    = blockIdx.x * 8 + jj;

    // --- pin this thread's recurrent weights in registers -------------------
    const float* Wg = (g == 0) ? Wf : ((g == 1) ? Wi : ((g == 2) ? Wc : Wo));
    const float* wrow = Wg + (size_t)j * 2048 + kg * 128;   // h-part cols
    ulonglong2 w[32];
#pragma unroll
    for (int q = 0; q < 32; ++q)
        w[q] = ((const ulonglong2*)wrow)[q];

    const unsigned long long barAddr = (unsigned long long)&g_bar;

    for (int t = 0; t < S_; ++t) {
        const float* __restrict__ hin  = g_hbuf[t & 1];
        float* __restrict__       hout = g_hbuf[(t + 1) & 1];

        // --- warp stages its own k-slice of h(t): 32 rows x 128 floats ------
        {
            const float* src = hin + kg * 128 + (lane << 2);
            float* dst = hs + kg * 128 + (lane << 2);
#pragma unroll 4
            for (int r = 0; r < 32; ++r)
                *(float4*)(dst + r * 1024) = *(const float4*)(src + r * 1024);
        }
        __syncwarp();

#pragma unroll 1
        for (int bb = 0; bb < 4; ++bb) {
            unsigned long long acc[8];
#pragma unroll
            for (int i = 0; i < 8; ++i) acc[i] = 0ull;

            const float* hsb = hs + (bb * 8) * 1024 + kg * 128;
#pragma unroll
            for (int q = 0; q < 32; ++q) {
                ulonglong2 wq = w[q];
#pragma unroll
                for (int i = 0; i < 8; ++i) {
                    ulonglong2 h2 = *(const ulonglong2*)(hsb + i * 1024 + (q << 2));
                    fma2(acc[i], h2.x, wq.x);
                    fma2(acc[i], h2.y, wq.y);
                }
            }
#pragma unroll
            for (int i = 0; i < 8; ++i) {
                float2 p = unpack2(acc[i]);
                red[kg * 288 + lane * 9 + i] = p.x + p.y;
            }
            __syncthreads();

            // reduce across the 8 k-slices; fold in GX (x-part + bias)
            {
                int out = tid & 31, bi = tid >> 5;
                float s = 0.0f;
#pragma unroll
                for (int kk = 0; kk < 8; ++kk)
                    s += red[kk * 288 + out * 9 + bi];
                int gg2 = out >> 3, jj2 = out & 7;
                int b = bb * 8 + bi;
                float gx = g_GX[(size_t)t * (B_ * G4_) + (size_t)b * G4_
                                + gg2 * 1024 + blockIdx.x * 8 + jj2];
                pre[gg2 * 256 + b * 8 + jj2] = s + gx;
            }
            __syncthreads();
        }

        // --- cell update: one (b, j) per thread ------------------------------
        {
            int b2  = tid >> 3;
            int jj2 = tid & 7;
            int j2  = blockIdx.x * 8 + jj2;
            float pf = pre[0 * 256 + b2 * 8 + jj2];
            float pi = pre[1 * 256 + b2 * 8 + jj2];
            float pc = pre[2 * 256 + b2 * 8 + jj2];
            float po = pre[3 * 256 + b2 * 8 + jj2];
            float fg = 1.0f / (1.0f + expf(-pf));
            float ig = 1.0f / (1.0f + expf(-pi));
            float cg = tanhf(pc);
            float og = 1.0f / (1.0f + expf(-po));
            float cold = g_c[b2 * H_ + j2];
            float cn = fg * cold + ig * cg;
            float hn = og * tanhf(cn);
            g_c[b2 * H_ + j2]  = cn;
            hout[b2 * H_ + j2] = hn;
            g_HS[((size_t)b2 * S_ + t) * H_ + j2] = hn;
        }

        // --- grid barrier (all 128 blocks co-resident) -----------------------
        __syncthreads();
        if (tid == 0) {
            asm volatile("fence.acq_rel.gpu;" ::: "memory");      // release h/c writes
            asm volatile("red.global.gpu.add.u32 [%0], 1;"
                         :: "l"(barAddr) : "memory");
            unsigned target = (unsigned)NBLK * (unsigned)(t + 1);
            unsigned v;
            do {
                asm volatile("ld.global.acquire.gpu.u32 %0, [%1];"
                             : "=r"(v) : "l"(barAddr) : "memory");
            } while (v < target);
        }
        __syncthreads();
    }
}

// ---------------- Phase 3: out[m][n] = HS[m,:] @ Wfc[n,:].T + bfc[n] --------
__global__ __launch_bounds__(256) void fc_gemm(
    const float* __restrict__ Wfc, const float* __restrict__ bfc,
    float* __restrict__ out)
{
    __shared__ float As[16][68];
    __shared__ float Bs[16][68];

    const int tid = threadIdx.x;
    const int m0 = blockIdx.y * 64;
    const int n0 = blockIdx.x * 64;
    const int tx = tid & 15;
    const int ty = tid >> 4;

    const int lrow = tid >> 2;
    const int lkq  = (tid & 3) * 4;

    const float* wrow = Wfc + (size_t)(n0 + lrow) * 1024;
    const float* arow = g_HS + (size_t)(m0 + lrow) * 1024;

    unsigned long long acc[4][2];
#pragma unroll
    for (int r = 0; r < 4; ++r) { acc[r][0] = 0ull; acc[r][1] = 0ull; }

    for (int k0 = 0; k0 < 1024; k0 += 16) {
        float4 av = *(const float4*)(arow + k0 + lkq);
        float4 bv = *(const float4*)(wrow + k0 + lkq);
        As[lkq + 0][lrow] = av.x; As[lkq + 1][lrow] = av.y;
        As[lkq + 2][lrow] = av.z; As[lkq + 3][lrow] = av.w;
        Bs[lkq + 0][lrow] = bv.x; Bs[lkq + 1][lrow] = bv.y;
        Bs[lkq + 2][lrow] = bv.z; Bs[lkq + 3][lrow] = bv.w;
        __syncthreads();
#pragma unroll
        for (int k = 0; k < 16; ++k) {
            float4 a4 = *(const float4*)&As[k][ty * 4];
            ulonglong2 b2 = *(const ulonglong2*)&Bs[k][tx * 4];
            unsigned long long a0 = splat2(a4.x);
            unsigned long long a1 = splat2(a4.y);
            unsigned long long a2 = splat2(a4.z);
            unsigned long long a3 = splat2(a4.w);
            fma2(acc[0][0], a0, b2.x); fma2(acc[0][1], a0, b2.y);
            fma2(acc[1][0], a1, b2.x); fma2(acc[1][1], a1, b2.y);
            fma2(acc[2][0], a2, b2.x); fma2(acc[2][1], a2, b2.y);
            fma2(acc[3][0], a3, b2.x); fma2(acc[3][1], a3, b2.y);
        }
        __syncthreads();
    }

    float bias[4];
#pragma unroll
    for (int c = 0; c < 4; ++c) bias[c] = bfc[n0 + tx * 4 + c];

#pragma unroll
    for (int r = 0; r < 4; ++r) {
        int m = m0 + ty * 4 + r;
        float2 p0 = unpack2(acc[r][0]);
        float2 p1 = unpack2(acc[r][1]);
        float4 v = make_float4(p0.x + bias[0], p0.y + bias[1],
                               p1.x + bias[2], p1.y + bias[3]);
        *(float4*)&out[(size_t)m * OUT_ + n0 + tx * 4] = v;
    }
}

// ---------------- launch ----------------------------------------------------
extern "C" void kernel_launch(void* const* d_in, const int* in_sizes, int n_in,
                              void* d_out, int out_size) {
    (void)in_sizes; (void)n_in; (void)out_size;
    const float* x   = (const float*)d_in[0];
    const float* Wf  = (const float*)d_in[1];
    const float* bf  = (const float*)d_in[2];
    const float* Wi  = (const float*)d_in[3];
    const float* bi  = (const float*)d_in[4];
    const float* Wc  = (const float*)d_in[5];
    const float* bc  = (const float*)d_in[6];
    const float* Wo  = (const float*)d_in[7];
    const float* bo  = (const float*)d_in[8];
    const float* Wfc = (const float*)d_in[9];
    const float* bfc = (const float*)d_in[10];
    float* out = (float*)d_out;

    const int smemBytes = (32768 + 2304 + 1024) * (int)sizeof(float); // 144,384 B
    cudaFuncSetAttribute(lstm_persistent,
                         cudaFuncAttributeMaxDynamicSharedMemorySize, smemBytes);

    init_state_kernel<<<128, 256>>>();

    // Phase 1: x-part of all 4 gates, all timesteps (fully parallel)
    gx_gemm<<<dim3(64, 256), 256>>>(x, Wf, Wi, Wc, Wo, bf, bi, bc, bo);

    // Phase 2: one persistent kernel for all 512 recurrent steps
    lstm_persistent<<<NBLK, 256, smemBytes>>>(Wf, Wi, Wc, Wo);

    // Phase 3: output projection
    fc_gemm<<<dim3(16, 256), 256>>>(Wfc, bfc, out);
}

// round 15
// speedup vs baseline: 1.2174x; 1.2174x over previous
#include <cuda_runtime.h>
#include <math.h>

#define B_    32
#define S_    512
#define IN_   1024
#define H_    1024
#define OUT_  1024
#define G4_   4096   // 4*H
#define NBLK  128

// ---------------- scratch (device globals; no allocation allowed) ----------
__device__ float g_GX[(size_t)S_ * B_ * G4_];   // [t][b][4H] x-part pre-activations (+bias)
__device__ float g_HS[(size_t)B_ * S_ * H_];    // [b][t][H]  hidden outputs
__device__ float g_hbuf[2][B_ * H_];            // double-buffered h
__device__ unsigned g_bar;                      // grid barrier counter

// ---------------- f32x2 packed helpers ------------------------------------
__device__ __forceinline__ unsigned long long splat2(float v) {
    unsigned long long r;
    asm("mov.b64 %0, {%1, %1};" : "=l"(r) : "f"(v));
    return r;
}
__device__ __forceinline__ void fma2(unsigned long long& d, unsigned long long a, unsigned long long b) {
    asm("fma.rn.f32x2 %0, %1, %2, %0;" : "+l"(d) : "l"(a), "l"(b));
}
__device__ __forceinline__ float2 unpack2(unsigned long long v) {
    float2 r;
    asm("mov.b64 {%0, %1}, %2;" : "=f"(r.x), "=f"(r.y) : "l"(v));
    return r;
}

// ---------------- init: zero h0, barrier -----------------------------------
__global__ void init_state_kernel() {
    int i = blockIdx.x * blockDim.x + threadIdx.x;
    if (i < B_ * H_) g_hbuf[0][i] = 0.0f;
    if (i == 0) g_bar = 0u;
}

// ============================================================================
// 128x128x16 fp32 GEMM core (A[M,K] row-major, B[N,K] row-major, C = A@B.T)
// 256 threads, 8x8 micro-tile, f32x2 packed along N, double-buffered loads.
// ============================================================================
#define GEMM_PROLOGUE()                                                        \
    __shared__ float As[16][132];                                              \
    __shared__ float Bs[16][132];                                              \
    const int tid = threadIdx.x;                                               \
    const int tx = tid & 15;                                                   \
    const int ty = tid >> 4;                                                   \
    const int r0  = (tid * 2) >> 2;          /* loader row for u=0 */          \
    const int kq0 = ((tid * 2) & 3) << 2;                                      \
    const int r1  = (tid * 2 + 1) >> 2;                                        \
    const int kq1 = ((tid * 2 + 1) & 3) << 2;                                  \
    unsigned long long acc[8][4];                                              \
    _Pragma("unroll")                                                          \
    for (int r = 0; r < 8; ++r)                                                \
        _Pragma("unroll")                                                      \
        for (int c = 0; c < 4; ++c) acc[r][c] = 0ull;

#define GEMM_MAIN(AROW0, AROW1, BROW0, BROW1)                                  \
    float4 ra0 = *(const float4*)((AROW0) + kq0);                              \
    float4 ra1 = *(const float4*)((AROW1) + kq1);                              \
    float4 rb0 = *(const float4*)((BROW0) + kq0);                              \
    float4 rb1 = *(const float4*)((BROW1) + kq1);                              \
    for (int k0 = 0; k0 < 1024; k0 += 16) {                                    \
        As[kq0 + 0][r0] = ra0.x; As[kq0 + 1][r0] = ra0.y;                      \
        As[kq0 + 2][r0] = ra0.z; As[kq0 + 3][r0] = ra0.w;                      \
        As[kq1 + 0][r1] = ra1.x; As[kq1 + 1][r1] = ra1.y;                      \
        As[kq1 + 2][r1] = ra1.z; As[kq1 + 3][r1] = ra1.w;                      \
        Bs[kq0 + 0][r0] = rb0.x; Bs[kq0 + 1][r0] = rb0.y;                      \
        Bs[kq0 + 2][r0] = rb0.z; Bs[kq0 + 3][r0] = rb0.w;                      \
        Bs[kq1 + 0][r1] = rb1.x; Bs[kq1 + 1][r1] = rb1.y;                      \
        Bs[kq1 + 2][r1] = rb1.z; Bs[kq1 + 3][r1] = rb1.w;                      \
        __syncthreads();                                                       \
        if (k0 + 16 < 1024) {                                                  \
            ra0 = *(const float4*)((AROW0) + k0 + 16 + kq0);                   \
            ra1 = *(const float4*)((AROW1) + k0 + 16 + kq1);                   \
            rb0 = *(const float4*)((BROW0) + k0 + 16 + kq0);                   \
            rb1 = *(const float4*)((BROW1) + k0 + 16 + kq1);                   \
        }                                                                      \
        _Pragma("unroll")                                                      \
        for (int k = 0; k < 16; ++k) {                                         \
            float4 a0 = *(const float4*)&As[k][ty * 8];                        \
            float4 a1 = *(const float4*)&As[k][ty * 8 + 4];                    \
            ulonglong2 b0 = *(const ulonglong2*)&Bs[k][tx * 8];                \
            ulonglong2 b1 = *(const ulonglong2*)&Bs[k][tx * 8 + 4];            \
            float av[8] = {a0.x, a0.y, a0.z, a0.w, a1.x, a1.y, a1.z, a1.w};    \
            _Pragma("unroll")                                                  \
            for (int r = 0; r < 8; ++r) {                                      \
                unsigned long long ar = splat2(av[r]);                         \
                fma2(acc[r][0], ar, b0.x); fma2(acc[r][1], ar, b0.y);          \
                fma2(acc[r][2], ar, b1.x); fma2(acc[r][3], ar, b1.y);          \
            }                                                                  \
        }                                                                      \
        __syncthreads();                                                       \
    }

// ---------------- Phase 1: GX = x @ Wx.T + bias -----------------------------
// M = B*S = 16384 (m = b*512 + t), N = 4096 (n = g*1024 + j), K = 1024.
__global__ __launch_bounds__(256, 2) void gx_gemm(
    const float* __restrict__ x,
    const float* __restrict__ Wf, const float* __restrict__ Wi,
    const float* __restrict__ Wc, const float* __restrict__ Wo,
    const float* __restrict__ bf, const float* __restrict__ bi,
    const float* __restrict__ bc, const float* __restrict__ bo)
{
    GEMM_PROLOGUE();
    const int m0 = blockIdx.y * 128;
    const int n0 = blockIdx.x * 128;

    const int gate = n0 >> 10;          // whole 128-wide tile is inside one gate
    const int jb   = n0 & 1023;
    const float* Wg = (gate == 0) ? Wf : ((gate == 1) ? Wi : ((gate == 2) ? Wc : Wo));
    const float* bb = (gate == 0) ? bf : ((gate == 1) ? bi : ((gate == 2) ? bc : bo));

    const float* arow0 = x + (size_t)(m0 + r0) * 1024;
    const float* arow1 = x + (size_t)(m0 + r1) * 1024;
    const float* brow0 = Wg + (size_t)(jb + r0) * 2048 + 1024;   // x-part columns
    const float* brow1 = Wg + (size_t)(jb + r1) * 2048 + 1024;

    GEMM_MAIN(arow0, arow1, brow0, brow1);

    float bias[8];
#pragma unroll
    for (int c = 0; c < 8; ++c) bias[c] = bb[jb + tx * 8 + c];

#pragma unroll
    for (int r = 0; r < 8; ++r) {
        int m  = m0 + ty * 8 + r;
        int b  = m >> 9;
        int tt = m & 511;
        float* dst = &g_GX[(size_t)(tt * 32 + b) * G4_ + n0 + tx * 8];
        float2 p0 = unpack2(acc[r][0]);
        float2 p1 = unpack2(acc[r][1]);
        float2 p2 = unpack2(acc[r][2]);
        float2 p3 = unpack2(acc[r][3]);
        *(float4*)(dst)     = make_float4(p0.x + bias[0], p0.y + bias[1],
                                          p1.x + bias[2], p1.y + bias[3]);
        *(float4*)(dst + 4) = make_float4(p2.x + bias[4], p2.y + bias[5],
                                          p3.x + bias[6], p3.y + bias[7]);
    }
}

// ---------------- Phase 3: out = HS @ Wfc.T + bfc ---------------------------
__global__ __launch_bounds__(256, 2) void fc_gemm(
    const float* __restrict__ Wfc, const float* __restrict__ bfc,
    float* __restrict__ out)
{
    GEMM_PROLOGUE();
    const int m0 = blockIdx.y * 128;
    const int n0 = blockIdx.x * 128;

    const float* arow0 = g_HS + (size_t)(m0 + r0) * 1024;
    const float* arow1 = g_HS + (size_t)(m0 + r1) * 1024;
    const float* brow0 = Wfc + (size_t)(n0 + r0) * 1024;
    const float* brow1 = Wfc + (size_t)(n0 + r1) * 1024;

    GEMM_MAIN(arow0, arow1, brow0, brow1);

    float bias[8];
#pragma unroll
    for (int c = 0; c < 8; ++c) bias[c] = bfc[n0 + tx * 8 + c];

#pragma unroll
    for (int r = 0; r < 8; ++r) {
        int m = m0 + ty * 8 + r;
        float* dst = &out[(size_t)m * OUT_ + n0 + tx * 8];
        float2 p0 = unpack2(acc[r][0]);
        float2 p1 = unpack2(acc[r][1]);
        float2 p2 = unpack2(acc[r][2]);
        float2 p3 = unpack2(acc[r][3]);
        *(float4*)(dst)     = make_float4(p0.x + bias[0], p0.y + bias[1],
                                          p1.x + bias[2], p1.y + bias[3]);
        *(float4*)(dst + 4) = make_float4(p2.x + bias[4], p2.y + bias[5],
                                          p3.x + bias[6], p3.y + bias[7]);
    }
}

// ---------------- Phase 2: persistent recurrent kernel ----------------------
// 128 blocks x 512 threads. Block bk owns hidden cols [bk*8, bk*8+8), all 4
// gates. 16 warps = k-slices of 64; lane = (gate, jj). Weights live in 16
// ulonglong2 registers per thread for the whole sequence. Cell state lives in
// a register of the update thread. Per step: batched-LDG h staging, GX
// register prefetch, fma block (no syncs), one reduce+cell-update, one grid
// barrier. smem = 128KB h + 72KB reduce = 200KB -> 1 block/SM, 128 <= 148 SMs
// so the hand-rolled barrier is deadlock-free.
__global__ __launch_bounds__(512, 1) void lstm_persistent(
    const float* __restrict__ Wf, const float* __restrict__ Wi,
    const float* __restrict__ Wc, const float* __restrict__ Wo)
{
    extern __shared__ float sm[];
    float* hs  = sm;                  // [32][1024]              = 32768 floats
    float* red = sm + 32768;          // [4 bb][16 kg][32 out][9] = 18432 floats

    const int tid  = threadIdx.x;
    const int kg   = tid >> 5;        // warp id = k-slice (0..15)
    const int lane = tid & 31;        // out = (g, jj)
    const int g    = lane >> 3;
    const int jj   = lane & 7;
    const int j    = blockIdx.x * 8 + jj;

    // update-thread mapping (tid < 256)
    const int rb  = tid >> 3;         // batch 0..31
    const int rjj = tid & 7;

    // --- pin recurrent weights in registers ---------------------------------
    const float* Wg = (g == 0) ? Wf : ((g == 1) ? Wi : ((g == 2) ? Wc : Wo));
    const float* wrow = Wg + (size_t)j * 2048 + kg * 64;   // h-part columns
    ulonglong2 w[16];
#pragma unroll
    for (int q = 0; q < 16; ++q)
        w[q] = ((const ulonglong2*)wrow)[q];

    float c_reg = 0.0f;               // cell state (only meaningful tid<256)
    const unsigned long long barAddr = (unsigned long long)&g_bar;

    for (int t = 0; t < S_; ++t) {
        const float* __restrict__ hin  = g_hbuf[t & 1];
        float* __restrict__       hout = g_hbuf[(t + 1) & 1];

        // --- prefetch GX for this step (used in the update) ------------------
        float gx0 = 0.f, gx1 = 0.f, gx2 = 0.f, gx3 = 0.f;
        if (tid < 256) {
            const float* gxr = g_GX + (size_t)t * (B_ * G4_)
                             + (size_t)rb * G4_ + blockIdx.x * 8 + rjj;
            gx0 = gxr[0];
            gx1 = gxr[1024];
            gx2 = gxr[2048];
            gx3 = gxr[3072];
        }

        // --- stage h(t) into smem: 8192 float4 over 512 threads, MLP 8 -------
        {
            const float4* src = (const float4*)hin;
            float4* dst = (float4*)hs;
            float4 tmp[8];
#pragma unroll
            for (int u = 0; u < 8; ++u) tmp[u] = src[tid + u * 512];
#pragma unroll
            for (int u = 0; u < 8; ++u) dst[tid + u * 512] = tmp[u];
#pragma unroll
            for (int u = 0; u < 8; ++u) tmp[u] = src[tid + (u + 8) * 512];
#pragma unroll
            for (int u = 0; u < 8; ++u) dst[tid + (u + 8) * 512] = tmp[u];
        }
        __syncthreads();

        // --- partial dot products over this warp's 64-wide k-slice -----------
#pragma unroll 1
        for (int bb = 0; bb < 4; ++bb) {
            unsigned long long acc[8];
#pragma unroll
            for (int i = 0; i < 8; ++i) acc[i] = 0ull;

            const float* hsb = hs + (bb * 8) * 1024 + kg * 64;
#pragma unroll
            for (int q = 0; q < 16; ++q) {
                ulonglong2 wq = w[q];
#pragma unroll
                for (int i = 0; i < 8; ++i) {
                    ulonglong2 h2 = *(const ulonglong2*)(hsb + i * 1024 + (q << 2));
                    fma2(acc[i], h2.x, wq.x);
                    fma2(acc[i], h2.y, wq.y);
                }
            }
            float* rslot = red + ((size_t)(bb * 16 + kg) * 32 + lane) * 9;
#pragma unroll
            for (int i = 0; i < 8; ++i) {
                float2 p = unpack2(acc[i]);
                rslot[i] = p.x + p.y;
            }
        }
        __syncthreads();

        // --- reduce across 16 k-slices + cell update (tid < 256) -------------
        if (tid < 256) {
            const int bbb = rb >> 3;
            const int bi  = rb & 7;
            float pr[4];
#pragma unroll
            for (int g2 = 0; g2 < 4; ++g2) {
                float s = 0.0f;
#pragma unroll
                for (int kk = 0; kk < 16; ++kk)
                    s += red[((size_t)(bbb * 16 + kk) * 32 + g2 * 8 + rjj) * 9 + bi];
                pr[g2] = s;
            }
            float pf = pr[0] + gx0;
            float pi = pr[1] + gx1;
            float pc = pr[2] + gx2;
            float po = pr[3] + gx3;
            float fg = 1.0f / (1.0f + expf(-pf));
            float ig = 1.0f / (1.0f + expf(-pi));
            float cg = tanhf(pc);
            float og = 1.0f / (1.0f + expf(-po));
            c_reg = fg * c_reg + ig * cg;
            float hn = og * tanhf(c_reg);
            int j2 = blockIdx.x * 8 + rjj;
            hout[rb * H_ + j2] = hn;
            g_HS[((size_t)rb * S_ + t) * H_ + j2] = hn;
        }

        // --- grid barrier (all 128 blocks co-resident) ------------------------
        __syncthreads();
        if (tid == 0) {
            asm volatile("fence.acq_rel.gpu;" ::: "memory");
            asm volatile("red.global.gpu.add.u32 [%0], 1;"
                         :: "l"(barAddr) : "memory");
            unsigned target = (unsigned)NBLK * (unsigned)(t + 1);
            unsigned v;
            do {
                asm volatile("ld.global.acquire.gpu.u32 %0, [%1];"
                             : "=r"(v) : "l"(barAddr) : "memory");
            } while (v < target);
        }
        __syncthreads();
    }
}

// ---------------- launch ----------------------------------------------------
extern "C" void kernel_launch(void* const* d_in, const int* in_sizes, int n_in,
                              void* d_out, int out_size) {
    (void)in_sizes; (void)n_in; (void)out_size;
    const float* x   = (const float*)d_in[0];
    const float* Wf  = (const float*)d_in[1];
    const float* bf  = (const float*)d_in[2];
    const float* Wi  = (const float*)d_in[3];
    const float* bi  = (const float*)d_in[4];
    const float* Wc  = (const float*)d_in[5];
    const float* bc  = (const float*)d_in[6];
    const float* Wo  = (const float*)d_in[7];
    const float* bo  = (const float*)d_in[8];
    const float* Wfc = (const float*)d_in[9];
    const float* bfc = (const float*)d_in[10];
    float* out = (float*)d_out;

    const int smemBytes = (32768 + 18432) * (int)sizeof(float);  // 204,800 B
    static int attrSet = 0;
    if (!attrSet) {
        cudaFuncSetAttribute(lstm_persistent,
                             cudaFuncAttributeMaxDynamicSharedMemorySize, smemBytes);
        attrSet = 1;
    }

    init_state_kernel<<<128, 256>>>();

    // Phase 1: x-part of all 4 gates, all timesteps (fully parallel)
    gx_gemm<<<dim3(32, 128), 256>>>(x, Wf, Wi, Wc, Wo, bf, bi, bc, bo);

    // Phase 2: one persistent kernel for all 512 recurrent steps
    lstm_persistent<<<NBLK, 512, smemBytes>>>(Wf, Wi, Wc, Wo);

    // Phase 3: output projection
    fc_gemm<<<dim3(8, 128), 256>>>(Wfc, bfc, out);
}

// round 16
// speedup vs baseline: 1.2421x; 1.0203x over previous
#include <cuda_runtime.h>
#include <math.h>

#define B_    32
#define S_    512
#define IN_   1024
#define H_    1024
#define OUT_  1024
#define G4_   4096   // 4*H
#define NBLK  128
#define HSTR  1028   // padded hs row stride (floats) — kills STS bank conflicts

// ---------------- scratch (device globals; no allocation allowed) ----------
__device__ float g_GX[(size_t)S_ * B_ * G4_];   // [t][b][4H] x-part pre-activations (+bias)
__device__ float g_HS[(size_t)B_ * S_ * H_];    // [b][t][H]  hidden outputs
__device__ float g_hbuf[2][B_ * H_];            // double-buffered h
__device__ unsigned g_bar;                      // grid barrier counter

// ---------------- f32x2 packed helpers ------------------------------------
__device__ __forceinline__ unsigned long long splat2(float v) {
    unsigned long long r;
    asm("mov.b64 %0, {%1, %1};" : "=l"(r) : "f"(v));
    return r;
}
__device__ __forceinline__ void fma2(unsigned long long& d, unsigned long long a, unsigned long long b) {
    asm("fma.rn.f32x2 %0, %1, %2, %0;" : "+l"(d) : "l"(a), "l"(b));
}
__device__ __forceinline__ float2 unpack2(unsigned long long v) {
    float2 r;
    asm("mov.b64 {%0, %1}, %2;" : "=f"(r.x), "=f"(r.y) : "l"(v));
    return r;
}

// ---------------- init: zero h0, barrier -----------------------------------
__global__ void init_state_kernel() {
    int i = blockIdx.x * blockDim.x + threadIdx.x;
    if (i < B_ * H_) g_hbuf[0][i] = 0.0f;
    if (i == 0) g_bar = 0u;
}

// ============================================================================
// 128x128x16 fp32 GEMM core, DOUBLE-BUFFERED smem: one __syncthreads per
// 16-k tile. A[M,K] row-major, B[N,K] row-major, C = A@B.T.
// 256 threads, 8x8 micro-tile, f32x2 packed along N.
// ============================================================================
#define GEMM_PROLOGUE()                                                        \
    __shared__ float As[2][16][132];                                           \
    __shared__ float Bs[2][16][132];                                           \
    const int tid = threadIdx.x;                                               \
    const int tx = tid & 15;                                                   \
    const int ty = tid >> 4;                                                   \
    const int r0  = (tid * 2) >> 2;                                            \
    const int kq0 = ((tid * 2) & 3) << 2;                                      \
    const int r1  = (tid * 2 + 1) >> 2;                                        \
    const int kq1 = ((tid * 2 + 1) & 3) << 2;                                  \
    unsigned long long acc[8][4];                                              \
    _Pragma("unroll")                                                          \
    for (int r = 0; r < 8; ++r)                                                \
        _Pragma("unroll")                                                      \
        for (int c = 0; c < 4; ++c) acc[r][c] = 0ull;

#define GEMM_MAIN(AROW0, AROW1, BROW0, BROW1)                                  \
    {                                                                          \
        float4 ra0 = *(const float4*)((AROW0) + kq0);                          \
        float4 ra1 = *(const float4*)((AROW1) + kq1);                          \
        float4 rb0 = *(const float4*)((BROW0) + kq0);                          \
        float4 rb1 = *(const float4*)((BROW1) + kq1);                          \
        As[0][kq0 + 0][r0] = ra0.x; As[0][kq0 + 1][r0] = ra0.y;                \
        As[0][kq0 + 2][r0] = ra0.z; As[0][kq0 + 3][r0] = ra0.w;                \
        As[0][kq1 + 0][r1] = ra1.x; As[0][kq1 + 1][r1] = ra1.y;                \
        As[0][kq1 + 2][r1] = ra1.z; As[0][kq1 + 3][r1] = ra1.w;                \
        Bs[0][kq0 + 0][r0] = rb0.x; Bs[0][kq0 + 1][r0] = rb0.y;                \
        Bs[0][kq0 + 2][r0] = rb0.z; Bs[0][kq0 + 3][r0] = rb0.w;                \
        Bs[0][kq1 + 0][r1] = rb1.x; Bs[0][kq1 + 1][r1] = rb1.y;                \
        Bs[0][kq1 + 2][r1] = rb1.z; Bs[0][kq1 + 3][r1] = rb1.w;                \
    }                                                                          \
    __syncthreads();                                                           \
    _Pragma("unroll 1")                                                        \
    for (int k0 = 0, p = 0; k0 < 1024; k0 += 16, p ^= 1) {                     \
        float4 na0, na1, nb0, nb1;                                             \
        const bool more = (k0 + 16 < 1024);                                    \
        if (more) {                                                            \
            na0 = *(const float4*)((AROW0) + k0 + 16 + kq0);                   \
            na1 = *(const float4*)((AROW1) + k0 + 16 + kq1);                   \
            nb0 = *(const float4*)((BROW0) + k0 + 16 + kq0);                   \
            nb1 = *(const float4*)((BROW1) + k0 + 16 + kq1);                   \
        }                                                                      \
        _Pragma("unroll")                                                      \
        for (int k = 0; k < 16; ++k) {                                         \
            float4 a0 = *(const float4*)&As[p][k][ty * 8];                     \
            float4 a1 = *(const float4*)&As[p][k][ty * 8 + 4];                 \
            ulonglong2 b0 = *(const ulonglong2*)&Bs[p][k][tx * 8];             \
            ulonglong2 b1 = *(const ulonglong2*)&Bs[p][k][tx * 8 + 4];         \
            float av[8] = {a0.x, a0.y, a0.z, a0.w, a1.x, a1.y, a1.z, a1.w};    \
            _Pragma("unroll")                                                  \
            for (int r = 0; r < 8; ++r) {                                      \
                unsigned long long ar = splat2(av[r]);                         \
                fma2(acc[r][0], ar, b0.x); fma2(acc[r][1], ar, b0.y);          \
                fma2(acc[r][2], ar, b1.x); fma2(acc[r][3], ar, b1.y);          \
            }                                                                  \
        }                                                                      \
        if (more) {                                                            \
            int q = p ^ 1;                                                     \
            As[q][kq0 + 0][r0] = na0.x; As[q][kq0 + 1][r0] = na0.y;            \
            As[q][kq0 + 2][r0] = na0.z; As[q][kq0 + 3][r0] = na0.w;            \
            As[q][kq1 + 0][r1] = na1.x; As[q][kq1 + 1][r1] = na1.y;            \
            As[q][kq1 + 2][r1] = na1.z; As[q][kq1 + 3][r1] = na1.w;            \
            Bs[q][kq0 + 0][r0] = nb0.x; Bs[q][kq0 + 1][r0] = nb0.y;            \
            Bs[q][kq0 + 2][r0] = nb0.z; Bs[q][kq0 + 3][r0] = nb0.w;            \
            Bs[q][kq1 + 0][r1] = nb1.x; Bs[q][kq1 + 1][r1] = nb1.y;            \
            Bs[q][kq1 + 2][r1] = nb1.z; Bs[q][kq1 + 3][r1] = nb1.w;            \
            __syncthreads();                                                   \
        }                                                                      \
    }

// ---------------- Phase 1: GX = x @ Wx.T + bias -----------------------------
// M = B*S = 16384 (m = b*512 + t), N = 4096 (n = g*1024 + j), K = 1024.
__global__ __launch_bounds__(256, 2) void gx_gemm(
    const float* __restrict__ x,
    const float* __restrict__ Wf, const float* __restrict__ Wi,
    const float* __restrict__ Wc, const float* __restrict__ Wo,
    const float* __restrict__ bf, const float* __restrict__ bi,
    const float* __restrict__ bc, const float* __restrict__ bo)
{
    GEMM_PROLOGUE();
    const int m0 = blockIdx.y * 128;
    const int n0 = blockIdx.x * 128;

    const int gate = n0 >> 10;          // whole 128-wide tile is inside one gate
    const int jb   = n0 & 1023;
    const float* Wg = (gate == 0) ? Wf : ((gate == 1) ? Wi : ((gate == 2) ? Wc : Wo));
    const float* bb = (gate == 0) ? bf : ((gate == 1) ? bi : ((gate == 2) ? bc : bo));

    const float* arow0 = x + (size_t)(m0 + r0) * 1024;
    const float* arow1 = x + (size_t)(m0 + r1) * 1024;
    const float* brow0 = Wg + (size_t)(jb + r0) * 2048 + 1024;   // x-part columns
    const float* brow1 = Wg + (size_t)(jb + r1) * 2048 + 1024;

    GEMM_MAIN(arow0, arow1, brow0, brow1);

    float bias[8];
#pragma unroll
    for (int c = 0; c < 8; ++c) bias[c] = bb[jb + tx * 8 + c];

#pragma unroll
    for (int r = 0; r < 8; ++r) {
        int m  = m0 + ty * 8 + r;
        int b  = m >> 9;
        int tt = m & 511;
        float* dst = &g_GX[(size_t)(tt * 32 + b) * G4_ + n0 + tx * 8];
        float2 p0 = unpack2(acc[r][0]);
        float2 p1 = unpack2(acc[r][1]);
        float2 p2 = unpack2(acc[r][2]);
        float2 p3 = unpack2(acc[r][3]);
        *(float4*)(dst)     = make_float4(p0.x + bias[0], p0.y + bias[1],
                                          p1.x + bias[2], p1.y + bias[3]);
        *(float4*)(dst + 4) = make_float4(p2.x + bias[4], p2.y + bias[5],
                                          p3.x + bias[6], p3.y + bias[7]);
    }
}

// ---------------- Phase 3: out = HS @ Wfc.T + bfc ---------------------------
__global__ __launch_bounds__(256, 2) void fc_gemm(
    const float* __restrict__ Wfc, const float* __restrict__ bfc,
    float* __restrict__ out)
{
    GEMM_PROLOGUE();
    const int m0 = blockIdx.y * 128;
    const int n0 = blockIdx.x * 128;

    const float* arow0 = g_HS + (size_t)(m0 + r0) * 1024;
    const float* arow1 = g_HS + (size_t)(m0 + r1) * 1024;
    const float* brow0 = Wfc + (size_t)(n0 + r0) * 1024;
    const float* brow1 = Wfc + (size_t)(n0 + r1) * 1024;

    GEMM_MAIN(arow0, arow1, brow0, brow1);

    float bias[8];
#pragma unroll
    for (int c = 0; c < 8; ++c) bias[c] = bfc[n0 + tx * 8 + c];

#pragma unroll
    for (int r = 0; r < 8; ++r) {
        int m = m0 + ty * 8 + r;
        float* dst = &out[(size_t)m * OUT_ + n0 + tx * 8];
        float2 p0 = unpack2(acc[r][0]);
        float2 p1 = unpack2(acc[r][1]);
        float2 p2 = unpack2(acc[r][2]);
        float2 p3 = unpack2(acc[r][3]);
        *(float4*)(dst)     = make_float4(p0.x + bias[0], p0.y + bias[1],
                                          p1.x + bias[2], p1.y + bias[3]);
        *(float4*)(dst + 4) = make_float4(p2.x + bias[4], p2.y + bias[5],
                                          p3.x + bias[6], p3.y + bias[7]);
    }
}

// ---------------- Phase 2: persistent recurrent kernel ----------------------
// 128 blocks x 512 threads (16 warps). Block bk owns hidden cols [bk*8,bk*8+8),
// all 4 gates; warp = 64-wide k-slice; lane = (gate, jj). Weights pinned in 16
// ulonglong2 registers/thread; cell state in a register. Per step:
//   - each warp stages ONLY ITS OWN 8KB h-slice (LDG.128 MLP 8) + __syncwarp
//     (no block-wide sync before the fma block)
//   - fma block writes per-kg partials to smem
//   - GX(t+1) prefetched here, hiding its DRAM latency under the sync
//   - one __syncthreads, reduce + cell update by 256 threads
//   - grid barrier (tid0 fence.acq_rel.gpu emits CCTL.IVALL -> L1 invalidated,
//     making the next step's cross-block h reads coherent)
__global__ __launch_bounds__(512, 1) void lstm_persistent(
    const float* __restrict__ Wf, const float* __restrict__ Wi,
    const float* __restrict__ Wc, const float* __restrict__ Wo)
{
    extern __shared__ float sm[];
    float* hs  = sm;                       // [32][HSTR]               = 32896 floats
    float* red = sm + 32 * HSTR;           // [4 bb][16 kg][32 out][9] = 18432 floats

    const int tid  = threadIdx.x;
    const int kg   = tid >> 5;             // warp id = k-slice (0..15)
    const int lane = tid & 31;             // out = (g, jj)
    const int g    = lane >> 3;
    const int jj   = lane & 7;
    const int j    = blockIdx.x * 8 + jj;

    // update-thread mapping (tid < 256)
    const int rb  = tid >> 3;              // batch 0..31
    const int rjj = tid & 7;

    // staging mapping: lane -> (row parity, float4 column) within own slice
    const int srow = lane >> 4;            // 0/1
    const int sc4  = (lane & 15) << 2;     // float offset 0..60

    // --- pin recurrent weights in registers ---------------------------------
    const float* Wg = (g == 0) ? Wf : ((g == 1) ? Wi : ((g == 2) ? Wc : Wo));
    const float* wrow = Wg + (size_t)j * 2048 + kg * 64;   // h-part columns
    ulonglong2 w[16];
#pragma unroll
    for (int q = 0; q < 16; ++q)
        w[q] = ((const ulonglong2*)wrow)[q];

    float c_reg = 0.0f;
    const unsigned long long barAddr = (unsigned long long)&g_bar;

    // --- GX prefetch for t = 0 ----------------------------------------------
    float gx0 = 0.f, gx1 = 0.f, gx2 = 0.f, gx3 = 0.f;
    if (tid < 256) {
        const float* gxr = g_GX + (size_t)rb * G4_ + blockIdx.x * 8 + rjj;
        gx0 = gxr[0]; gx1 = gxr[1024]; gx2 = gxr[2048]; gx3 = gxr[3072];
    }

    for (int t = 0; t < S_; ++t) {
        const float* __restrict__ hin  = g_hbuf[t & 1];
        float* __restrict__       hout = g_hbuf[(t + 1) & 1];

        // --- warp stages its OWN 64-wide k-slice: 32 rows x 64 floats --------
        {
            const float* src = hin + kg * 64 + sc4;
            float* dst = hs + kg * 64 + sc4;
            float4 tmp[8];
#pragma unroll
            for (int u = 0; u < 8; ++u)
                tmp[u] = *(const float4*)(src + (size_t)(2 * u + srow) * 1024);
#pragma unroll
            for (int u = 0; u < 8; ++u)
                *(float4*)(dst + (size_t)(2 * u + srow) * HSTR) = tmp[u];
#pragma unroll
            for (int u = 0; u < 8; ++u)
                tmp[u] = *(const float4*)(src + (size_t)(2 * u + 16 + srow) * 1024);
#pragma unroll
            for (int u = 0; u < 8; ++u)
                *(float4*)(dst + (size_t)(2 * u + 16 + srow) * HSTR) = tmp[u];
        }
        __syncwarp();

        // --- partial dot products over this warp's 64-wide k-slice -----------
#pragma unroll 1
        for (int bb = 0; bb < 4; ++bb) {
            unsigned long long acc[8];
#pragma unroll
            for (int i = 0; i < 8; ++i) acc[i] = 0ull;

            const float* hsb = hs + (size_t)(bb * 8) * HSTR + kg * 64;
#pragma unroll
            for (int q = 0; q < 16; ++q) {
                ulonglong2 wq = w[q];
#pragma unroll
                for (int i = 0; i < 8; ++i) {
                    ulonglong2 h2 = *(const ulonglong2*)(hsb + (size_t)i * HSTR + (q << 2));
                    fma2(acc[i], h2.x, wq.x);
                    fma2(acc[i], h2.y, wq.y);
                }
            }
            float* rslot = red + ((size_t)(bb * 16 + kg) * 32 + lane) * 9;
#pragma unroll
            for (int i = 0; i < 8; ++i) {
                float2 p = unpack2(acc[i]);
                rslot[i] = p.x + p.y;
            }
        }

        // --- prefetch GX for NEXT step (independent of h; hides DRAM lat) ----
        float ngx0 = 0.f, ngx1 = 0.f, ngx2 = 0.f, ngx3 = 0.f;
        if (tid < 256) {
            int tn = (t + 1 < S_) ? (t + 1) : t;
            const float* gxr = g_GX + (size_t)tn * (B_ * G4_)
                             + (size_t)rb * G4_ + blockIdx.x * 8 + rjj;
            ngx0 = gxr[0]; ngx1 = gxr[1024]; ngx2 = gxr[2048]; ngx3 = gxr[3072];
        }
        __syncthreads();

        // --- reduce across 16 k-slices + cell update (tid < 256) -------------
        if (tid < 256) {
            const int bbb = rb >> 3;
            const int bi  = rb & 7;
            float pr[4];
#pragma unroll
            for (int g2 = 0; g2 < 4; ++g2) {
                float s = 0.0f;
#pragma unroll
                for (int kk = 0; kk < 16; ++kk)
                    s += red[((size_t)(bbb * 16 + kk) * 32 + g2 * 8 + rjj) * 9 + bi];
                pr[g2] = s;
            }
            float pf = pr[0] + gx0;
            float pi = pr[1] + gx1;
            float pc = pr[2] + gx2;
            float po = pr[3] + gx3;
            float fg = 1.0f / (1.0f + expf(-pf));
            float ig = 1.0f / (1.0f + expf(-pi));
            float cg = tanhf(pc);
            float og = 1.0f / (1.0f + expf(-po));
            c_reg = fg * c_reg + ig * cg;
            float hn = og * tanhf(c_reg);
            int j2 = blockIdx.x * 8 + rjj;
            hout[rb * H_ + j2] = hn;
            g_HS[((size_t)rb * S_ + t) * H_ + j2] = hn;
        }
        gx0 = ngx0; gx1 = ngx1; gx2 = ngx2; gx3 = ngx3;

        // --- grid barrier (all 128 blocks co-resident, 1 block/SM) -----------
        __syncthreads();
        if (tid == 0) {
            asm volatile("fence.acq_rel.gpu;" ::: "memory");   // release + IVALL
            asm volatile("red.global.gpu.add.u32 [%0], 1;"
                         :: "l"(barAddr) : "memory");
            unsigned target = (unsigned)NBLK * (unsigned)(t + 1);
            unsigned v;
            do {
                asm volatile("ld.global.acquire.gpu.u32 %0, [%1];"
                             : "=r"(v) : "l"(barAddr) : "memory");
            } while (v < target);
        }
        __syncthreads();
    }
}

// ---------------- launch ----------------------------------------------------
extern "C" void kernel_launch(void* const* d_in, const int* in_sizes, int n_in,
                              void* d_out, int out_size) {
    (void)in_sizes; (void)n_in; (void)out_size;
    const float* x   = (const float*)d_in[0];
    const float* Wf  = (const float*)d_in[1];
    const float* bf  = (const float*)d_in[2];
    const float* Wi  = (const float*)d_in[3];
    const float* bi  = (const float*)d_in[4];
    const float* Wc  = (const float*)d_in[5];
    const float* bc  = (const float*)d_in[6];
    const float* Wo  = (const float*)d_in[7];
    const float* bo  = (const float*)d_in[8];
    const float* Wfc = (const float*)d_in[9];
    const float* bfc = (const float*)d_in[10];
    float* out = (float*)d_out;

    const int smemBytes = (32 * HSTR + 18432) * (int)sizeof(float);  // 205,312 B
    static int attrSet = 0;
    if (!attrSet) {
        cudaFuncSetAttribute(lstm_persistent,
                             cudaFuncAttributeMaxDynamicSharedMemorySize, smemBytes);
        attrSet = 1;
    }

    init_state_kernel<<<128, 256>>>();

    // Phase 1: x-part of all 4 gates, all timesteps (fully parallel)
    gx_gemm<<<dim3(32, 128), 256>>>(x, Wf, Wi, Wc, Wo, bf, bi, bc, bo);

    // Phase 2: one persistent kernel for all 512 recurrent steps
    lstm_persistent<<<NBLK, 512, smemBytes>>>(Wf, Wi, Wc, Wo);

    // Phase 3: output projection
    fc_gemm<<<dim3(8, 128), 256>>>(Wfc, bfc, out);
}

// round 17
// speedup vs baseline: 1.2472x; 1.0041x over previous
#include <cuda_runtime.h>
#include <math.h>

#define B_    32
#define S_    512
#define IN_   1024
#define H_    1024
#define OUT_  1024
#define G4_   4096   // 4*H
#define NBLK  128
#define HSTR  1028   // padded hs row stride (floats) — kills STS bank conflicts

// ---------------- scratch (device globals; no allocation allowed) ----------
__device__ float g_GX[(size_t)S_ * B_ * G4_];   // [t][b][4H] x-part pre-activations (+bias)
__device__ float g_HS[(size_t)B_ * S_ * H_];    // [b][t][H]  hidden outputs
__device__ float g_hbuf[2][B_ * H_];            // double-buffered h
__device__ unsigned g_bar;                      // grid barrier counter

// ---------------- f32x2 packed helpers ------------------------------------
__device__ __forceinline__ unsigned long long splat2(float v) {
    unsigned long long r;
    asm("mov.b64 %0, {%1, %1};" : "=l"(r) : "f"(v));
    return r;
}
__device__ __forceinline__ void fma2(unsigned long long& d, unsigned long long a, unsigned long long b) {
    asm("fma.rn.f32x2 %0, %1, %2, %0;" : "+l"(d) : "l"(a), "l"(b));
}
__device__ __forceinline__ float2 unpack2(unsigned long long v) {
    float2 r;
    asm("mov.b64 {%0, %1}, %2;" : "=f"(r.x), "=f"(r.y) : "l"(v));
    return r;
}

// ---------------- fast activations (ex2.approx, rel err ~2^-22) ------------
__device__ __forceinline__ float fsigmoid(float x) {
    float e;
    asm("ex2.approx.f32 %0, %1;" : "=f"(e) : "f"(x * -1.4426950408889634f));
    return __fdividef(1.0f, 1.0f + e);
}
__device__ __forceinline__ float ftanh(float x) {
    float e;
    asm("ex2.approx.f32 %0, %1;" : "=f"(e) : "f"(x * 2.8853900817779268f));
    return 1.0f - __fdividef(2.0f, e + 1.0f);
}

// ---------------- init: zero h0, barrier -----------------------------------
__global__ void init_state_kernel() {
    int i = blockIdx.x * blockDim.x + threadIdx.x;
    if (i < B_ * H_) g_hbuf[0][i] = 0.0f;
    if (i == 0) g_bar = 0u;
}

// ============================================================================
// 128x128x16 fp32 GEMM core, DOUBLE-BUFFERED smem: one __syncthreads per
// 16-k tile. A[M,K] row-major, B[N,K] row-major, C = A@B.T.
// 256 threads, 8x8 micro-tile, f32x2 packed along N.
// ============================================================================
#define GEMM_PROLOGUE()                                                        \
    __shared__ float As[2][16][132];                                           \
    __shared__ float Bs[2][16][132];                                           \
    const int tid = threadIdx.x;                                               \
    const int tx = tid & 15;                                                   \
    const int ty = tid >> 4;                                                   \
    const int r0  = (tid * 2) >> 2;                                            \
    const int kq0 = ((tid * 2) & 3) << 2;                                      \
    const int r1  = (tid * 2 + 1) >> 2;                                        \
    const int kq1 = ((tid * 2 + 1) & 3) << 2;                                  \
    unsigned long long acc[8][4];                                              \
    _Pragma("unroll")                                                          \
    for (int r = 0; r < 8; ++r)                                                \
        _Pragma("unroll")                                                      \
        for (int c = 0; c < 4; ++c) acc[r][c] = 0ull;

#define GEMM_MAIN(AROW0, AROW1, BROW0, BROW1)                                  \
    {                                                                          \
        float4 ra0 = *(const float4*)((AROW0) + kq0);                          \
        float4 ra1 = *(const float4*)((AROW1) + kq1);                          \
        float4 rb0 = *(const float4*)((BROW0) + kq0);                          \
        float4 rb1 = *(const float4*)((BROW1) + kq1);                          \
        As[0][kq0 + 0][r0] = ra0.x; As[0][kq0 + 1][r0] = ra0.y;                \
        As[0][kq0 + 2][r0] = ra0.z; As[0][kq0 + 3][r0] = ra0.w;                \
        As[0][kq1 + 0][r1] = ra1.x; As[0][kq1 + 1][r1] = ra1.y;                \
        As[0][kq1 + 2][r1] = ra1.z; As[0][kq1 + 3][r1] = ra1.w;                \
        Bs[0][kq0 + 0][r0] = rb0.x; Bs[0][kq0 + 1][r0] = rb0.y;                \
        Bs[0][kq0 + 2][r0] = rb0.z; Bs[0][kq0 + 3][r0] = rb0.w;                \
        Bs[0][kq1 + 0][r1] = rb1.x; Bs[0][kq1 + 1][r1] = rb1.y;                \
        Bs[0][kq1 + 2][r1] = rb1.z; Bs[0][kq1 + 3][r1] = rb1.w;                \
    }                                                                          \
    __syncthreads();                                                           \
    _Pragma("unroll 1")                                                        \
    for (int k0 = 0, p = 0; k0 < 1024; k0 += 16, p ^= 1) {                     \
        float4 na0, na1, nb0, nb1;                                             \
        const bool more = (k0 + 16 < 1024);                                    \
        if (more) {                                                            \
            na0 = *(const float4*)((AROW0) + k0 + 16 + kq0);                   \
            na1 = *(const float4*)((AROW1) + k0 + 16 + kq1);                   \
            nb0 = *(const float4*)((BROW0) + k0 + 16 + kq0);                   \
            nb1 = *(const float4*)((BROW1) + k0 + 16 + kq1);                   \
        }                                                                      \
        _Pragma("unroll")                                                      \
        for (int k = 0; k < 16; ++k) {                                         \
            float4 a0 = *(const float4*)&As[p][k][ty * 8];                     \
            float4 a1 = *(const float4*)&As[p][k][ty * 8 + 4];                 \
            ulonglong2 b0 = *(const ulonglong2*)&Bs[p][k][tx * 8];             \
            ulonglong2 b1 = *(const ulonglong2*)&Bs[p][k][tx * 8 + 4];         \
            float av[8] = {a0.x, a0.y, a0.z, a0.w, a1.x, a1.y, a1.z, a1.w};    \
            _Pragma("unroll")                                                  \
            for (int r = 0; r < 8; ++r) {                                      \
                unsigned long long ar = splat2(av[r]);                         \
                fma2(acc[r][0], ar, b0.x); fma2(acc[r][1], ar, b0.y);          \
                fma2(acc[r][2], ar, b1.x); fma2(acc[r][3], ar, b1.y);          \
            }                                                                  \
        }                                                                      \
        if (more) {                                                            \
            int q = p ^ 1;                                                     \
            As[q][kq0 + 0][r0] = na0.x; As[q][kq0 + 1][r0] = na0.y;            \
            As[q][kq0 + 2][r0] = na0.z; As[q][kq0 + 3][r0] = na0.w;            \
            As[q][kq1 + 0][r1] = na1.x; As[q][kq1 + 1][r1] = na1.y;            \
            As[q][kq1 + 2][r1] = na1.z; As[q][kq1 + 3][r1] = na1.w;            \
            Bs[q][kq0 + 0][r0] = nb0.x; Bs[q][kq0 + 1][r0] = nb0.y;            \
            Bs[q][kq0 + 2][r0] = nb0.z; Bs[q][kq0 + 3][r0] = nb0.w;            \
            Bs[q][kq1 + 0][r1] = nb1.x; Bs[q][kq1 + 1][r1] = nb1.y;            \
            Bs[q][kq1 + 2][r1] = nb1.z; Bs[q][kq1 + 3][r1] = nb1.w;            \
            __syncthreads();                                                   \
        }                                                                      \
    }

// ---------------- Phase 1: GX = x @ Wx.T + bias -----------------------------
// M = B*S = 16384 (m = b*512 + t), N = 4096 (n = g*1024 + j), K = 1024.
__global__ __launch_bounds__(256, 2) void gx_gemm(
    const float* __restrict__ x,
    const float* __restrict__ Wf, const float* __restrict__ Wi,
    const float* __restrict__ Wc, const float* __restrict__ Wo,
    const float* __restrict__ bf, const float* __restrict__ bi,
    const float* __restrict__ bc, const float* __restrict__ bo)
{
    GEMM_PROLOGUE();
    const int m0 = blockIdx.y * 128;
    const int n0 = blockIdx.x * 128;

    const int gate = n0 >> 10;          // whole 128-wide tile is inside one gate
    const int jb   = n0 & 1023;
    const float* Wg = (gate == 0) ? Wf : ((gate == 1) ? Wi : ((gate == 2) ? Wc : Wo));
    const float* bb = (gate == 0) ? bf : ((gate == 1) ? bi : ((gate == 2) ? bc : bo));

    const float* arow0 = x + (size_t)(m0 + r0) * 1024;
    const float* arow1 = x + (size_t)(m0 + r1) * 1024;
    const float* brow0 = Wg + (size_t)(jb + r0) * 2048 + 1024;   // x-part columns
    const float* brow1 = Wg + (size_t)(jb + r1) * 2048 + 1024;

    GEMM_MAIN(arow0, arow1, brow0, brow1);

    float bias[8];
#pragma unroll
    for (int c = 0; c < 8; ++c) bias[c] = bb[jb + tx * 8 + c];

#pragma unroll
    for (int r = 0; r < 8; ++r) {
        int m  = m0 + ty * 8 + r;
        int b  = m >> 9;
        int tt = m & 511;
        float* dst = &g_GX[(size_t)(tt * 32 + b) * G4_ + n0 + tx * 8];
        float2 p0 = unpack2(acc[r][0]);
        float2 p1 = unpack2(acc[r][1]);
        float2 p2 = unpack2(acc[r][2]);
        float2 p3 = unpack2(acc[r][3]);
        *(float4*)(dst)     = make_float4(p0.x + bias[0], p0.y + bias[1],
                                          p1.x + bias[2], p1.y + bias[3]);
        *(float4*)(dst + 4) = make_float4(p2.x + bias[4], p2.y + bias[5],
                                          p3.x + bias[6], p3.y + bias[7]);
    }
}

// ---------------- Phase 3: out = HS @ Wfc.T + bfc ---------------------------
__global__ __launch_bounds__(256, 2) void fc_gemm(
    const float* __restrict__ Wfc, const float* __restrict__ bfc,
    float* __restrict__ out)
{
    GEMM_PROLOGUE();
    const int m0 = blockIdx.y * 128;
    const int n0 = blockIdx.x * 128;

    const float* arow0 = g_HS + (size_t)(m0 + r0) * 1024;
    const float* arow1 = g_HS + (size_t)(m0 + r1) * 1024;
    const float* brow0 = Wfc + (size_t)(n0 + r0) * 1024;
    const float* brow1 = Wfc + (size_t)(n0 + r1) * 1024;

    GEMM_MAIN(arow0, arow1, brow0, brow1);

    float bias[8];
#pragma unroll
    for (int c = 0; c < 8; ++c) bias[c] = bfc[n0 + tx * 8 + c];

#pragma unroll
    for (int r = 0; r < 8; ++r) {
        int m = m0 + ty * 8 + r;
        float* dst = &out[(size_t)m * OUT_ + n0 + tx * 8];
        float2 p0 = unpack2(acc[r][0]);
        float2 p1 = unpack2(acc[r][1]);
        float2 p2 = unpack2(acc[r][2]);
        float2 p3 = unpack2(acc[r][3]);
        *(float4*)(dst)     = make_float4(p0.x + bias[0], p0.y + bias[1],
                                          p1.x + bias[2], p1.y + bias[3]);
        *(float4*)(dst + 4) = make_float4(p2.x + bias[4], p2.y + bias[5],
                                          p3.x + bias[6], p3.y + bias[7]);
    }
}

// ---------------- Phase 2: persistent recurrent kernel ----------------------
// 128 blocks x 512 threads (16 warps). Block bk owns hidden cols [bk*8,bk*8+8),
// all 4 gates; warp = 64-wide k-slice; lane = (gate, jj). Weights pinned in 16
// ulonglong2 registers/thread; cell state in a register. Per step:
//   - PIPELINED staging: warp stages its k-slice in 4 chunks of 8 batch rows
//     (4 LDG.128/lane); fma block for chunk bb runs while chunk bb+1's LDGs
//     are in flight. __syncwarp only — no block-wide sync before compute.
//   - GX(t+1) prefetched after the fma block (hides DRAM latency)
//   - one __syncthreads, reduce + cell update by 256 threads (fast sigmoids)
//   - grid barrier (tid0 fence.acq_rel.gpu -> release + L1 invalidate)
__global__ __launch_bounds__(512, 1) void lstm_persistent(
    const float* __restrict__ Wf, const float* __restrict__ Wi,
    const float* __restrict__ Wc, const float* __restrict__ Wo)
{
    extern __shared__ float sm[];
    float* hs  = sm;                       // [32][HSTR]               = 32896 floats
    float* red = sm + 32 * HSTR;           // [4 bb][16 kg][32 out][9] = 18432 floats

    const int tid  = threadIdx.x;
    const int kg   = tid >> 5;             // warp id = k-slice (0..15)
    const int lane = tid & 31;             // out = (g, jj)
    const int g    = lane >> 3;
    const int jj   = lane & 7;
    const int j    = blockIdx.x * 8 + jj;

    // update-thread mapping (tid < 256)
    const int rb  = tid >> 3;              // batch 0..31
    const int rjj = tid & 7;

    // staging mapping: lane -> (row parity within chunk, float4 column)
    const int srow = lane >> 4;            // 0/1
    const int scol = (lane & 15) << 2;     // float offset 0..60

    // --- pin recurrent weights in registers ---------------------------------
    const float* Wg = (g == 0) ? Wf : ((g == 1) ? Wi : ((g == 2) ? Wc : Wo));
    const float* wrow = Wg + (size_t)j * 2048 + kg * 64;   // h-part columns
    ulonglong2 w[16];
#pragma unroll
    for (int q = 0; q < 16; ++q)
        w[q] = ((const ulonglong2*)wrow)[q];

    float c_reg = 0.0f;
    const unsigned long long barAddr = (unsigned long long)&g_bar;

    // --- GX prefetch for t = 0 ----------------------------------------------
    float gx0 = 0.f, gx1 = 0.f, gx2 = 0.f, gx3 = 0.f;
    if (tid < 256) {
        const float* gxr = g_GX + (size_t)rb * G4_ + blockIdx.x * 8 + rjj;
        gx0 = gxr[0]; gx1 = gxr[1024]; gx2 = gxr[2048]; gx3 = gxr[3072];
    }

    for (int t = 0; t < S_; ++t) {
        const float* __restrict__ hin  = g_hbuf[t & 1];
        float* __restrict__       hout = g_hbuf[(t + 1) & 1];

        const float* sbase = hin + kg * 64 + scol;   // this warp's slice
        float* dbase = hs + kg * 64 + scol;

        // --- prefetch chunk 0 (batch rows 0..7 of own k-slice) ---------------
        float4 v0, v1, v2, v3;
        v0 = *(const float4*)(sbase + (size_t)(srow + 0) * 1024);
        v1 = *(const float4*)(sbase + (size_t)(srow + 2) * 1024);
        v2 = *(const float4*)(sbase + (size_t)(srow + 4) * 1024);
        v3 = *(const float4*)(sbase + (size_t)(srow + 6) * 1024);

#pragma unroll
        for (int bb = 0; bb < 4; ++bb) {
            // store current chunk to smem, make visible warp-wide
            *(float4*)(dbase + (size_t)(bb * 8 + srow + 0) * HSTR) = v0;
            *(float4*)(dbase + (size_t)(bb * 8 + srow + 2) * HSTR) = v1;
            *(float4*)(dbase + (size_t)(bb * 8 + srow + 4) * HSTR) = v2;
            *(float4*)(dbase + (size_t)(bb * 8 + srow + 6) * HSTR) = v3;
            __syncwarp();

            // issue LDGs for next chunk (in flight under the fma block)
            if (bb < 3) {
                v0 = *(const float4*)(sbase + (size_t)(bb * 8 + 8 + srow + 0) * 1024);
                v1 = *(const float4*)(sbase + (size_t)(bb * 8 + 8 + srow + 2) * 1024);
                v2 = *(const float4*)(sbase + (size_t)(bb * 8 + 8 + srow + 4) * 1024);
                v3 = *(const float4*)(sbase + (size_t)(bb * 8 + 8 + srow + 6) * 1024);
            }

            // fma block over this chunk's 8 batch rows
            unsigned long long acc[8];
#pragma unroll
            for (int i = 0; i < 8; ++i) acc[i] = 0ull;

            const float* hsb = hs + (size_t)(bb * 8) * HSTR + kg * 64;
#pragma unroll
            for (int q = 0; q < 16; ++q) {
                ulonglong2 wq = w[q];
#pragma unroll
                for (int i = 0; i < 8; ++i) {
                    ulonglong2 h2 = *(const ulonglong2*)(hsb + (size_t)i * HSTR + (q << 2));
                    fma2(acc[i], h2.x, wq.x);
                    fma2(acc[i], h2.y, wq.y);
                }
            }
            float* rslot = red + ((size_t)(bb * 16 + kg) * 32 + lane) * 9;
#pragma unroll
            for (int i = 0; i < 8; ++i) {
                float2 p = unpack2(acc[i]);
                rslot[i] = p.x + p.y;
            }
        }

        // --- prefetch GX for NEXT step (independent of h; hides DRAM lat) ----
        float ngx0 = 0.f, ngx1 = 0.f, ngx2 = 0.f, ngx3 = 0.f;
        if (tid < 256) {
            int tn = (t + 1 < S_) ? (t + 1) : t;
            const float* gxr = g_GX + (size_t)tn * (B_ * G4_)
                             + (size_t)rb * G4_ + blockIdx.x * 8 + rjj;
            ngx0 = gxr[0]; ngx1 = gxr[1024]; ngx2 = gxr[2048]; ngx3 = gxr[3072];
        }
        __syncthreads();

        // --- reduce across 16 k-slices + cell update (tid < 256) -------------
        if (tid < 256) {
            const int bbb = rb >> 3;
            const int bi  = rb & 7;
            float pr[4];
#pragma unroll
            for (int g2 = 0; g2 < 4; ++g2) {
                float s = 0.0f;
#pragma unroll
                for (int kk = 0; kk < 16; ++kk)
                    s += red[((size_t)(bbb * 16 + kk) * 32 + g2 * 8 + rjj) * 9 + bi];
                pr[g2] = s;
            }
            float fg = fsigmoid(pr[0] + gx0);
            float ig = fsigmoid(pr[1] + gx1);
            float cg = ftanh(pr[2] + gx2);
            float og = fsigmoid(pr[3] + gx3);
            c_reg = fg * c_reg + ig * cg;
            float hn = og * ftanh(c_reg);
            int j2 = blockIdx.x * 8 + rjj;
            hout[rb * H_ + j2] = hn;
            g_HS[((size_t)rb * S_ + t) * H_ + j2] = hn;
        }
        gx0 = ngx0; gx1 = ngx1; gx2 = ngx2; gx3 = ngx3;

        // --- grid barrier (all 128 blocks co-resident, 1 block/SM) -----------
        __syncthreads();
        if (tid == 0) {
            asm volatile("fence.acq_rel.gpu;" ::: "memory");   // release + IVALL
            asm volatile("red.global.gpu.add.u32 [%0], 1;"
                         :: "l"(barAddr) : "memory");
            unsigned target = (unsigned)NBLK * (unsigned)(t + 1);
            unsigned v;
            do {
                asm volatile("ld.global.acquire.gpu.u32 %0, [%1];"
                             : "=r"(v) : "l"(barAddr) : "memory");
            } while (v < target);
        }
        __syncthreads();
    }
}

// ---------------- launch ----------------------------------------------------
extern "C" void kernel_launch(void* const* d_in, const int* in_sizes, int n_in,
                              void* d_out, int out_size) {
    (void)in_sizes; (void)n_in; (void)out_size;
    const float* x   = (const float*)d_in[0];
    const float* Wf  = (const float*)d_in[1];
    const float* bf  = (const float*)d_in[2];
    const float* Wi  = (const float*)d_in[3];
    const float* bi  = (const float*)d_in[4];
    const float* Wc  = (const float*)d_in[5];
    const float* bc  = (const float*)d_in[6];
    const float* Wo  = (const float*)d_in[7];
    const float* bo  = (const float*)d_in[8];
    const float* Wfc = (const float*)d_in[9];
    const float* bfc = (const float*)d_in[10];
    float* out = (float*)d_out;

    const int smemBytes = (32 * HSTR + 18432) * (int)sizeof(float);  // 205,312 B
    static int attrSet = 0;
    if (!attrSet) {
        cudaFuncSetAttribute(lstm_persistent,
                             cudaFuncAttributeMaxDynamicSharedMemorySize, smemBytes);
        attrSet = 1;
    }

    init_state_kernel<<<128, 256>>>();

    // Phase 1: x-part of all 4 gates, all timesteps (fully parallel)
    gx_gemm<<<dim3(32, 128), 256>>>(x, Wf, Wi, Wc, Wo, bf, bi, bc, bo);

    // Phase 2: one persistent kernel for all 512 recurrent steps
    lstm_persistent<<<NBLK, 512, smemBytes>>>(Wf, Wi, Wc, Wo);

    // Phase 3: output projection
    fc_gemm<<<dim3(8, 128), 256>>>(Wfc, bfc, out);
}